// round 16
// baseline (speedup 1.0000x reference)
#include <cuda_runtime.h>
#include <cstdint>

#define NB   16          // batch
#define C    256         // channels
#define CH   128         // C/2 hidden / selected count
#define HW   16384       // 128*128 spatial
#define HW4  4096        // HW / 4 (float4)

__device__ float g_z[NB * C];     // per (n,c) channel means
__device__ int   g_dst[NB * C];   // g_dst[n*C + c] = output slot of channel c

// ---------------------------------------------------------------------------
// Kernel 1: channel means (EXACT R6 code — 41.4us, 6.6 TB/s, 31 regs).
// Default-cached reads leave the TAIL of x L2-resident for the scatter.
// ---------------------------------------------------------------------------
__global__ __launch_bounds__(256) void mean_kernel(const float* __restrict__ x)
{
    const int nc = blockIdx.x;
    const float4* __restrict__ p =
        reinterpret_cast<const float4*>(x + (size_t)nc * HW);

    float s = 0.0f;
    #pragma unroll
    for (int k = 0; k < HW4 / 256; ++k) {
        float4 v = p[threadIdx.x + k * 256];
        s += (v.x + v.y) + (v.z + v.w);
    }
    #pragma unroll
    for (int o = 16; o > 0; o >>= 1)
        s += __shfl_xor_sync(0xFFFFFFFFu, s, o);

    __shared__ float red[8];
    const int lane = threadIdx.x & 31, wid = threadIdx.x >> 5;
    if (lane == 0) red[wid] = s;
    __syncthreads();
    if (threadIdx.x == 0) {
        float t = 0.0f;
        #pragma unroll
        for (int w = 0; w < 8; ++w) t += red[w];
        g_z[nc] = t * (1.0f / (float)HW);
    }
}

// ---------------------------------------------------------------------------
// Kernel 2: MLP + sigmoid + stable rank (EXACT R6 code, ~4.5us).
// ---------------------------------------------------------------------------
__global__ __launch_bounds__(256) void mlp_rank_kernel(
    const float* __restrict__ W1, const float* __restrict__ b1,
    const float* __restrict__ W2, const float* __restrict__ b2)
{
    const int n    = blockIdx.x;
    const int t    = threadIdx.x;
    const int lane = t & 31;
    const int wid  = t >> 5;          // 8 warps

    __shared__ __align__(16) float z[C];
    __shared__ __align__(16) float h[CH];
    __shared__ float sc[C];

    z[t] = g_z[n * C + t];
    __syncthreads();

    const float4* __restrict__ z4 = reinterpret_cast<const float4*>(z);

    // h = relu(z @ W1.T + b1): warp 'wid' computes outputs wid*16 .. +15
    #pragma unroll
    for (int ii = 0; ii < 16; ++ii) {
        const int i = wid * 16 + ii;
        const float4* __restrict__ w4 =
            reinterpret_cast<const float4*>(W1 + i * C);       // 64 float4
        float4 wa = w4[lane], wb = w4[lane + 32];
        float4 za = z4[lane], zb = z4[lane + 32];
        float a = wa.x * za.x;
        a = fmaf(wa.y, za.y, a); a = fmaf(wa.z, za.z, a); a = fmaf(wa.w, za.w, a);
        a = fmaf(wb.x, zb.x, a); a = fmaf(wb.y, zb.y, a);
        a = fmaf(wb.z, zb.z, a); a = fmaf(wb.w, zb.w, a);
        #pragma unroll
        for (int o = 16; o > 0; o >>= 1)
            a += __shfl_xor_sync(0xFFFFFFFFu, a, o);
        if (lane == 0) {
            float v = a + b1[i];
            h[i] = v > 0.0f ? v : 0.0f;
        }
    }
    __syncthreads();

    const float4* __restrict__ h4 = reinterpret_cast<const float4*>(h);

    // scores = sigmoid(h @ W2.T + b2): warp 'wid' computes outputs wid*32 ..
    #pragma unroll
    for (int ii = 0; ii < 32; ++ii) {
        const int i = wid * 32 + ii;
        const float4* __restrict__ w4 =
            reinterpret_cast<const float4*>(W2 + i * CH);      // 32 float4
        float4 wa = w4[lane];
        float4 ha = h4[lane];
        float a = wa.x * ha.x;
        a = fmaf(wa.y, ha.y, a); a = fmaf(wa.z, ha.z, a); a = fmaf(wa.w, ha.w, a);
        #pragma unroll
        for (int o = 16; o > 0; o >>= 1)
            a += __shfl_xor_sync(0xFFFFFFFFu, a, o);
        if (lane == 0)
            sc[i] = 1.0f / (1.0f + expf(-(a + b2[i])));
    }
    __syncthreads();

    // Stable descending rank (matches jnp.argsort(-scores)):
    const float mys = sc[t];
    int rank = 0;
    #pragma unroll 8
    for (int j = 0; j < C; ++j) {
        float sj = sc[j];
        rank += (sj > mys) || (sj == mys && j < t);
    }
    g_dst[n * C + t] = rank;
}

// ---------------------------------------------------------------------------
// Kernel 3: SCATTER copy (EXACT R15 code — measured 75.9us, DRAM 80%).
// Reverse order consumes the L2-resident tail newest-first. __ldcs reads:
// hits don't re-allocate, misses don't pollute. __stcs stores: streaming.
// Output layout: [selected (NB,CH,H,W)] then [remaining (NB,CH,H,W)].
// ---------------------------------------------------------------------------
__global__ __launch_bounds__(256) void scatter_kernel(
    const float* __restrict__ x, float* __restrict__ out)
{
    const int b    = (NB * C - 1) - blockIdx.x;     // reverse order
    const int n    = b >> 8;
    const int slot = __ldg(&g_dst[b]);

    const float4* __restrict__ src =
        reinterpret_cast<const float4*>(x + (size_t)b * HW);   // linear read

    size_t dst_ch;
    if (slot < CH) dst_ch = (size_t)n * CH + slot;                          // selected
    else           dst_ch = (size_t)NB * CH + (size_t)n * CH + (slot - CH); // remaining
    float4* __restrict__ dst = reinterpret_cast<float4*>(out + dst_ch * HW);

    #pragma unroll
    for (int half = 0; half < 2; ++half) {
        const int base = half * (HW4 / 2) + threadIdx.x;
        float4 r[8];
        #pragma unroll
        for (int k = 0; k < 8; ++k)
            r[k] = __ldcs(&src[base + k * 256]);
        #pragma unroll
        for (int k = 0; k < 8; ++k)
            __stcs(&dst[base + k * 256], r[k]);
    }
}

// ---------------------------------------------------------------------------
extern "C" void kernel_launch(void* const* d_in, const int* in_sizes, int n_in,
                              void* d_out, int out_size)
{
    const float* x  = (const float*)d_in[0];
    const float* W1 = (const float*)d_in[1];
    const float* b1 = (const float*)d_in[2];
    const float* W2 = (const float*)d_in[3];
    const float* b2 = (const float*)d_in[4];
    float* out = (float*)d_out;

    mean_kernel<<<NB * C, 256>>>(x);
    mlp_rank_kernel<<<NB, 256>>>(W1, b1, W2, b2);
    scatter_kernel<<<NB * C, 256>>>(x, out);
}